// round 1
// baseline (speedup 1.0000x reference)
#include <cuda_runtime.h>
#include <math.h>

// Problem dims
#define NSAMP 3
#define SSYM  512
#define FDIM  20
#define NLIN  11
#define NOUT  9
#define HID   2048
#define HIN   13824      // NSAMP*SSYM*NOUT
#define NO_   (NSAMP*SSYM)

// Scratch (device globals; no allocation allowed)
__device__ float g_v[HIN];
__device__ float g_h1[HID];
__device__ float g_h2[HID];
__device__ float g_h3[HID];
__device__ float g_lin[NO_];

__device__ __forceinline__ float sigmoidf_(float x) { return 1.0f / (1.0f + expf(-x)); }

// ---------------------------------------------------------------------------
// Kernel 1: front end. One block per symbol s (512 blocks, 128 threads).
// Warps 0..2 handle sample b: inorm over F=20, DFT 20->11, bilinear, leakyrelu.
// Then softmax across the 3 samples per (s,k) and write v.
// ---------------------------------------------------------------------------
__global__ void front_kernel(const float* __restrict__ wax,
                             const float* __restrict__ blw,
                             const float* __restrict__ blb) {
    __shared__ float ctab[FDIM], stab[FDIM];
    __shared__ float sx [NSAMP][FDIM];
    __shared__ float sre[NSAMP][NLIN], sim[NSAMP][NLIN];
    __shared__ float szz[NSAMP][NOUT];

    const int s   = blockIdx.x;
    const int tid = threadIdx.x;

    if (tid < FDIM) {
        float th = 6.2831853071795864769f * (float)tid / 20.0f;
        ctab[tid] = cosf(th);
        stab[tid] = sinf(th);
    }
    __syncthreads();

    const int warp = tid >> 5, lane = tid & 31;
    if (warp < NSAMP) {
        const int b = warp;
        // InstanceNorm over F=20
        float x = 0.0f;
        if (lane < FDIM) x = wax[(b * SSYM + s) * FDIM + lane];
        float sum = x;
        #pragma unroll
        for (int off = 16; off; off >>= 1) sum += __shfl_xor_sync(0xffffffffu, sum, off);
        float mean = sum * (1.0f / 20.0f);
        float d = (lane < FDIM) ? (x - mean) : 0.0f;
        float sq = d * d;
        #pragma unroll
        for (int off = 16; off; off >>= 1) sq += __shfl_xor_sync(0xffffffffu, sq, off);
        float inv = rsqrtf(sq * (1.0f / 20.0f) + 1e-9f);
        if (lane < FDIM) sx[b][lane] = d * inv;
        __syncwarp();

        // rfft (direct DFT): X[m] = sum_n x[n] * exp(-2*pi*i*m*n/20), m in [0,10]
        if (lane < NLIN) {
            float re = 0.0f, im = 0.0f;
            #pragma unroll
            for (int n = 0; n < FDIM; n++) {
                int r = (lane * n) % FDIM;
                float xn = sx[b][n];
                re += xn * ctab[r];
                im -= xn * stab[r];
            }
            sre[b][lane] = re;
            sim[b][lane] = im;
        }
        __syncwarp();

        // Bilinear: z[k] = real^T * B_k * imag + blb[k]; leaky relu
        if (lane < NOUT) {
            const float* Bk = blw + lane * (NLIN * NLIN);
            float z = 0.0f;
            #pragma unroll
            for (int i = 0; i < NLIN; i++) {
                float t = 0.0f;
                #pragma unroll
                for (int j = 0; j < NLIN; j++) t = fmaf(Bk[i * NLIN + j], sim[b][j], t);
                z = fmaf(sre[b][i], t, z);
            }
            z += blb[lane];
            z = z > 0.0f ? z : 0.01f * z;
            szz[b][lane] = z;
        }
    }
    __syncthreads();

    // Softmax across b (3 values) per (s,k), write v[s*27 + b*9 + k]
    if (tid < NSAMP * NOUT) {
        const int b = tid / NOUT, k = tid % NOUT;
        float z0 = szz[0][k], z1 = szz[1][k], z2 = szz[2][k];
        float m  = fmaxf(z0, fmaxf(z1, z2));
        float e0 = expf(z0 - m), e1 = expf(z1 - m), e2 = expf(z2 - m);
        float den = e0 + e1 + e2;
        float eb  = (b == 0) ? e0 : (b == 1) ? e1 : e2;
        g_v[s * (NSAMP * NOUT) + b * NOUT + k] = eb / den;
    }
}

// ---------------------------------------------------------------------------
// Kernels 2-4: fused LSTM-cell matvec. One block per hidden unit j.
// Gate order (torch): i, f, g, o. f-gate rows are never read (c0 = 0),
// w_hh never read (h0 = 0). h[j] = sigmoid(o)*tanh(sigmoid(i)*tanh(g)).
// STAGE selects in/out scratch buffers at compile time.
// ---------------------------------------------------------------------------
template<int IN, int NT, int STAGE>
__global__ void __launch_bounds__(NT)
lstm_cell_kernel(const float* __restrict__ W,
                 const float* __restrict__ b_ih,
                 const float* __restrict__ b_hh) {
    const float* __restrict__ x =
        (STAGE == 0) ? g_v : (STAGE == 1) ? g_h1 : g_h2;
    float* __restrict__ hout =
        (STAGE == 0) ? g_h1 : (STAGE == 1) ? g_h2 : g_h3;

    const int j   = blockIdx.x;
    const int tid = threadIdx.x;

    const float4* __restrict__ x4 = (const float4*)x;
    const float4* __restrict__ w0 = (const float4*)(W + (size_t)j * IN);                 // i gate
    const float4* __restrict__ w1 = (const float4*)(W + (size_t)(j + 2 * HID) * IN);     // g gate
    const float4* __restrict__ w2 = (const float4*)(W + (size_t)(j + 3 * HID) * IN);     // o gate

    float acc0 = 0.0f, acc1 = 0.0f, acc2 = 0.0f;
    for (int t = tid; t < IN / 4; t += NT) {
        float4 v4 = x4[t];
        float4 a = w0[t];
        acc0 += a.x * v4.x + a.y * v4.y + a.z * v4.z + a.w * v4.w;
        float4 b = w1[t];
        acc1 += b.x * v4.x + b.y * v4.y + b.z * v4.z + b.w * v4.w;
        float4 c = w2[t];
        acc2 += c.x * v4.x + c.y * v4.y + c.z * v4.z + c.w * v4.w;
    }

    #pragma unroll
    for (int off = 16; off; off >>= 1) {
        acc0 += __shfl_xor_sync(0xffffffffu, acc0, off);
        acc1 += __shfl_xor_sync(0xffffffffu, acc1, off);
        acc2 += __shfl_xor_sync(0xffffffffu, acc2, off);
    }
    __shared__ float red[NT / 32][3];
    const int warp = tid >> 5, lane = tid & 31;
    if (lane == 0) { red[warp][0] = acc0; red[warp][1] = acc1; red[warp][2] = acc2; }
    __syncthreads();
    if (tid == 0) {
        float di = 0.0f, dg = 0.0f, dob = 0.0f;
        #pragma unroll
        for (int w = 0; w < NT / 32; w++) { di += red[w][0]; dg += red[w][1]; dob += red[w][2]; }
        float gi = di  + b_ih[j]            + b_hh[j];
        float gg = dg  + b_ih[j + 2 * HID]  + b_hh[j + 2 * HID];
        float go = dob + b_ih[j + 3 * HID]  + b_hh[j + 3 * HID];
        float c  = sigmoidf_(gi) * tanhf(gg);
        hout[j]  = sigmoidf_(go) * tanhf(c);
    }
}

// ---------------------------------------------------------------------------
// Kernel 5: final linear. One block per output row (1536 blocks).
// ---------------------------------------------------------------------------
template<int NT>
__global__ void __launch_bounds__(NT)
linear_kernel(const float* __restrict__ W, const float* __restrict__ bias) {
    const int j   = blockIdx.x;
    const int tid = threadIdx.x;
    const float4* __restrict__ x4 = (const float4*)g_h3;
    const float4* __restrict__ wr = (const float4*)(W + (size_t)j * HID);
    float acc = 0.0f;
    for (int t = tid; t < HID / 4; t += NT) {
        float4 v4 = x4[t];
        float4 a  = wr[t];
        acc += a.x * v4.x + a.y * v4.y + a.z * v4.z + a.w * v4.w;
    }
    #pragma unroll
    for (int off = 16; off; off >>= 1) acc += __shfl_xor_sync(0xffffffffu, acc, off);
    __shared__ float red[NT / 32];
    const int warp = tid >> 5, lane = tid & 31;
    if (lane == 0) red[warp] = acc;
    __syncthreads();
    if (tid == 0) {
        float s = 0.0f;
        #pragma unroll
        for (int w = 0; w < NT / 32; w++) s += red[w];
        g_lin[j] = s + bias[j];
    }
}

// ---------------------------------------------------------------------------
// Kernel 6: inorm over S=512 + leaky relu + softmax over S. 3 blocks x 512.
// ---------------------------------------------------------------------------
__device__ __forceinline__ float blk512_sum(float v, float* red) {
    __syncthreads();
    const int warp = threadIdx.x >> 5, lane = threadIdx.x & 31;
    #pragma unroll
    for (int off = 16; off; off >>= 1) v += __shfl_xor_sync(0xffffffffu, v, off);
    if (lane == 0) red[warp] = v;
    __syncthreads();
    float r = (threadIdx.x < 16) ? red[threadIdx.x] : 0.0f;
    if (warp == 0) {
        #pragma unroll
        for (int off = 8; off; off >>= 1) r += __shfl_xor_sync(0xffffffffu, r, off);
        if (lane == 0) red[0] = r;
    }
    __syncthreads();
    return red[0];
}

__device__ __forceinline__ float blk512_max(float v, float* red) {
    __syncthreads();
    const int warp = threadIdx.x >> 5, lane = threadIdx.x & 31;
    #pragma unroll
    for (int off = 16; off; off >>= 1) v = fmaxf(v, __shfl_xor_sync(0xffffffffu, v, off));
    if (lane == 0) red[warp] = v;
    __syncthreads();
    float r = (threadIdx.x < 16) ? red[threadIdx.x] : -3.4e38f;
    if (warp == 0) {
        #pragma unroll
        for (int off = 8; off; off >>= 1) r = fmaxf(r, __shfl_xor_sync(0xffffffffu, r, off));
        if (lane == 0) red[0] = r;
    }
    __syncthreads();
    return red[0];
}

__global__ void post_kernel(float* __restrict__ out) {
    __shared__ float red[16];
    const int b = blockIdx.x, tid = threadIdx.x;
    float x = g_lin[b * SSYM + tid];

    float mean = blk512_sum(x, red) * (1.0f / 512.0f);
    float d    = x - mean;
    float var  = blk512_sum(d * d, red) * (1.0f / 512.0f);
    float xn   = d * rsqrtf(var + 1e-9f);
    float lr   = xn > 0.0f ? xn : 0.01f * xn;
    float mx   = blk512_max(lr, red);
    float e    = expf(lr - mx);
    float den  = blk512_sum(e, red);
    out[b * SSYM + tid] = e / den;
}

// ---------------------------------------------------------------------------
// Launch
// ---------------------------------------------------------------------------
extern "C" void kernel_launch(void* const* d_in, const int* in_sizes, int n_in,
                              void* d_out, int out_size) {
    const float* wax   = (const float*)d_in[0];
    const float* blw   = (const float*)d_in[1];
    const float* blb   = (const float*)d_in[2];
    const float* w_ih0 = (const float*)d_in[3];
    // d_in[4] = w_hh0 (unused: h0 == 0)
    const float* b_ih0 = (const float*)d_in[5];
    const float* b_hh0 = (const float*)d_in[6];
    const float* w_ih1 = (const float*)d_in[7];
    const float* b_ih1 = (const float*)d_in[9];
    const float* b_hh1 = (const float*)d_in[10];
    const float* w_ih2 = (const float*)d_in[11];
    const float* b_ih2 = (const float*)d_in[13];
    const float* b_hh2 = (const float*)d_in[14];
    const float* lin_w = (const float*)d_in[15];
    const float* lin_b = (const float*)d_in[16];

    front_kernel<<<SSYM, 128>>>(wax, blw, blb);
    lstm_cell_kernel<HIN, 256, 0><<<HID, 256>>>(w_ih0, b_ih0, b_hh0);
    lstm_cell_kernel<HID, 128, 1><<<HID, 128>>>(w_ih1, b_ih1, b_hh1);
    lstm_cell_kernel<HID, 128, 2><<<HID, 128>>>(w_ih2, b_ih2, b_hh2);
    linear_kernel<128><<<NO_, 128>>>(lin_w, lin_b);
    post_kernel<<<NSAMP, 512>>>((float*)d_out);
}